// round 8
// baseline (speedup 1.0000x reference)
#include <cuda_runtime.h>
#include <math.h>

#define NB   8
#define ND   768
#define NCH  3
#define NMIX 5
#define H    10
#define NS   10
#define PI2f 6.283185307179586f
#define ZITTERf 1e-4f
#define INV_TEMP 10.0f
#define LOG2E 1.44269504088896341f

#define NJC 24              // j-chunks in feat
#define JC  32              // ND/NJC
#define ITILE 384           // i-range per feat block (3 i per thread)
#define NI_T  2             // ND/ITILE
#define NT2   3             // feat2 i-tiles of 256

#define OJT 192             // out threads (each owns 4 consecutive j)
#define OIT 16              // i-tile in out kernel (ND/OIT = 48)

#define TBLP   1984         // float2 pair-entries per (b,c); 3*TBLP*8 = 47616B shared
#define TSCALE 220.0f       // entries per unit |d| (covers |d| <= 9.0)
#define TCLAMP 1982.0f
#define FUSED_BLOCKS (NB * NCH * TBLP / 256)   // 186
#define FEAT2_BLOCKS (NB * NCH * NT2)          // 72

// cross-kernel scratch (__device__ globals per allocation rules)
__device__ float g_facc[NB * NCH][NJC][NMIX][ND];   // feat partials, coalesced in i
__device__ float g_hpart[NB * NCH][NT2][H];
__device__ float g_w[NB * NCH * NMIX];
__device__ float g_diag[NCH];
__device__ __align__(16) float2 g_ftab2[NB * NCH][TBLP];
__device__ int g_cnt;
__device__ int g_flag;

__device__ __forceinline__ float ex2f_(float x) {
    float y; asm("ex2.approx.f32 %0, %1;" : "=f"(y) : "f"(x)); return y;
}

// ---------------------------------------------------------------------------
// Kernel 1: pairwise SM-kernel j-reduction with split accumulators.
// block = (b, c, i-tile 384, j-chunk 32); 128 threads, 3 i's per thread.
// Inner loop per (i,m): MUL + EX2 + 2 FMA. i-side rotation applied after loop.
// ---------------------------------------------------------------------------
__global__ void __launch_bounds__(128) feat_kernel(
    const float* __restrict__ xc, const float* __restrict__ yc,
    const float* __restrict__ mu, const float* __restrict__ inv_std)
{
    if (blockIdx.x == 0 && threadIdx.x == 0) { g_cnt = 0; g_flag = 0; }

    int bid   = blockIdx.x;
    int chunk = bid % NJC;
    int r     = bid / NJC;
    int tile  = r % NI_T;
    int bc    = r / NI_T;
    int c     = bc % NCH;
    int b     = bc / NCH;
    int tid   = threadIdx.x;

    __shared__ float4 jt[JC][3];

    float km2[NMIX], pm[NMIX];
#pragma unroll
    for (int m = 0; m < NMIX; m++) {
        float iv = inv_std[m];
        km2[m] = -0.5f * PI2f * PI2f * iv * iv * LOG2E;
        pm[m]  = PI2f * mu[m];
    }

    int j0 = chunk * JC;
    if (tid < JC) {
        float xv = xc[(b * ND + j0 + tid) * NCH + c];
        float yv = yc[(b * ND + j0 + tid) * NCH + c];
        float cy[NMIX], sy[NMIX];
#pragma unroll
        for (int m = 0; m < NMIX; m++) {
            float s, co;
            __sincosf(pm[m] * xv, &s, &co);
            cy[m] = co * yv;
            sy[m] = s * yv;
        }
        jt[tid][0] = make_float4(cy[0], cy[1], cy[2], cy[3]);
        jt[tid][1] = make_float4(cy[4], sy[0], sy[1], sy[2]);
        jt[tid][2] = make_float4(sy[3], sy[4], xv, 0.f);
    }

    int i0 = tile * ITILE + tid;
    int i1 = i0 + 128;
    int i2 = i0 + 256;
    float xi0 = xc[(b * ND + i0) * NCH + c];
    float xi1 = xc[(b * ND + i1) * NCH + c];
    float xi2 = xc[(b * ND + i2) * NCH + c];

    float A0[NMIX], B0[NMIX], A1[NMIX], B1[NMIX], A2[NMIX], B2[NMIX];
#pragma unroll
    for (int m = 0; m < NMIX; m++) {
        A0[m] = B0[m] = A1[m] = B1[m] = A2[m] = B2[m] = 0.f;
    }
    __syncthreads();

#pragma unroll 2
    for (int j = 0; j < JC; j++) {
        float4 t0 = jt[j][0];
        float4 t1 = jt[j][1];
        float4 t2 = jt[j][2];
        float cy[NMIX] = {t0.x, t0.y, t0.z, t0.w, t1.x};
        float sy[NMIX] = {t1.y, t1.z, t1.w, t2.x, t2.y};
        float xj = t2.z;
        float d0 = xi0 - xj, d20 = d0 * d0;
        float d1 = xi1 - xj, d21 = d1 * d1;
        float d2 = xi2 - xj, d22 = d2 * d2;
#pragma unroll
        for (int m = 0; m < NMIX; m++) {
            float e0 = ex2f_(km2[m] * d20);
            float e1 = ex2f_(km2[m] * d21);
            float e2 = ex2f_(km2[m] * d22);
            A0[m] = fmaf(e0, cy[m], A0[m]);
            B0[m] = fmaf(e0, sy[m], B0[m]);
            A1[m] = fmaf(e1, cy[m], A1[m]);
            B1[m] = fmaf(e1, sy[m], B1[m]);
            A2[m] = fmaf(e2, cy[m], A2[m]);
            B2[m] = fmaf(e2, sy[m], B2[m]);
        }
    }

    // apply i-side rotation once per (i,m)
#pragma unroll
    for (int m = 0; m < NMIX; m++) {
        float s0, c0, s1, c1, s2, c2;
        __sincosf(pm[m] * xi0, &s0, &c0);
        __sincosf(pm[m] * xi1, &s1, &c1);
        __sincosf(pm[m] * xi2, &s2, &c2);
        g_facc[bc][chunk][m][i0] = fmaf(c0, A0[m], s0 * B0[m]);
        g_facc[bc][chunk][m][i1] = fmaf(c1, A1[m], s1 * B1[m]);
        g_facc[bc][chunk][m][i2] = fmaf(c2, A2[m], s2 * B2[m]);
    }
}

// ---------------------------------------------------------------------------
// Kernel 2 (fused): feat2 (blocks 0..71) -> arrival counter -> block 0 runs
// MLP layers 2-5 + Gumbel-softmax + diag -> flag -> all 186 blocks build the
// per-(b,c) pair-packed lookup tables.
// ---------------------------------------------------------------------------
__global__ void __launch_bounds__(256) fused_mid_kernel(
    const float* __restrict__ yc,
    const float* __restrict__ W1, const float* __restrict__ b1,
    const float* __restrict__ likerr, const float* __restrict__ unif,
    const float* __restrict__ W2, const float* __restrict__ b2,
    const float* __restrict__ W3, const float* __restrict__ b3,
    const float* __restrict__ W4, const float* __restrict__ b4,
    const float* __restrict__ W5, const float* __restrict__ b5,
    const float* __restrict__ mu, const float* __restrict__ inv_std)
{
    int blk = blockIdx.x;
    int tid = threadIdx.x;

    __shared__ float sh_h[256][H];

    // ---- phase A: feat2 (layer-1 + partial i-reduction) on blocks 0..71 ----
    if (blk < FEAT2_BLOCKS) {
        int tile = blk % NT2;
        int bc   = blk / NT2;
        int c    = bc % NCH;
        int b    = bc / NCH;
        int i    = tile * 256 + tid;

        float yi = yc[(b * ND + i) * NCH + c];
        float tif[NMIX + 1];
#pragma unroll
        for (int m = 0; m < NMIX; m++) {
            float s = 0.f;
#pragma unroll
            for (int ch = 0; ch < NJC; ch++) s += g_facc[bc][ch][m][i];
            tif[m] = s + ZITTERf * yi;
        }
        tif[NMIX] = yi;

#pragma unroll
        for (int k = 0; k < H; k++) {
            float s = b1[k];
#pragma unroll
            for (int t = 0; t < NMIX + 1; t++) s = fmaf(W1[k * (NMIX + 1) + t], tif[t], s);
            sh_h[tid][k] = fmaxf(s, 0.f);
        }
        __syncthreads();

        if (tid < H) {
            float s = 0.f;
            for (int t = 0; t < 256; t++) s += sh_h[t][tid];
            g_hpart[bc][tile][tid] = s;
        }
        __syncthreads();
        if (tid == 0) { __threadfence(); atomicAdd(&g_cnt, 1); }
    }

    // ---- phase B: block 0 waits for all feat2 blocks, runs the MLP ----
    if (blk == 0) {
        if (tid == 0) { while (atomicAdd(&g_cnt, 0) < FEAT2_BLOCKS) {} __threadfence(); }
        __syncthreads();

        __shared__ float sh_h0[NB][NCH * H];
        __shared__ float sh_a[NB][H];
        __shared__ float sh_b[NB][H];
        __shared__ float sh_ll[NB][NCH * NMIX];
        __shared__ float sh_sm[NB][NS][NCH][NMIX];

        if (tid < NB * NCH) {
            int b = tid / NCH, c = tid % NCH;
            for (int k = 0; k < H; k++) {
                float s = 0.f;
#pragma unroll
                for (int tt = 0; tt < NT2; tt++) s += g_hpart[b * NCH + c][tt][k];
                sh_h0[b][c * H + k] = s * (1.0f / ND);
            }
        }
        if (tid < NCH) {
            float l = fminf(fmaxf(likerr[tid], 0.1f), 1.0f);
            g_diag[tid] = ZITTERf + l * l;
        }
        __syncthreads();

        if (tid < NB * H) {                       // layer 2
            int b = tid / H, k = tid % H;
            float s = b2[k];
            for (int u = 0; u < NCH * H; u++) s = fmaf(W2[k * (NCH * H) + u], sh_h0[b][u], s);
            sh_a[b][k] = fmaxf(s, 0.f);
        }
        __syncthreads();
        if (tid < NB * H) {                       // layer 3
            int b = tid / H, k = tid % H;
            float s = b3[k];
            for (int u = 0; u < H; u++) s = fmaf(W3[k * H + u], sh_a[b][u], s);
            sh_b[b][k] = fmaxf(s, 0.f);
        }
        __syncthreads();
        if (tid < NB * H) {                       // layer 4
            int b = tid / H, k = tid % H;
            float s = b4[k];
            for (int u = 0; u < H; u++) s = fmaf(W4[k * H + u], sh_b[b][u], s);
            sh_a[b][k] = fmaxf(s, 0.f);
        }
        __syncthreads();
        if (tid < NB * NCH * NMIX) {              // layer 5 -> logits
            int b = tid / (NCH * NMIX), n = tid % (NCH * NMIX);
            float s = b5[n];
            for (int u = 0; u < H; u++) s = fmaf(W5[n * H + u], sh_a[b][u], s);
            sh_ll[b][n] = s;
        }
        __syncthreads();

        if (tid < NB * NS * NCH) {                // gumbel softmax per (b,s,c)
            int b = tid / (NS * NCH);
            int rem = tid % (NS * NCH);
            int s = rem / NCH, c = rem % NCH;
            float z[NMIX], mx = -1e30f;
#pragma unroll
            for (int m = 0; m < NMIX; m++) {
                float u = unif[((b * NS + s) * NCH + c) * NMIX + m];
                float g = -__logf(-__logf(u + 1e-20f));
                z[m] = (g + sh_ll[b][c * NMIX + m]) * INV_TEMP;
                mx = fmaxf(mx, z[m]);
            }
            float sum = 0.f, e[NMIX];
#pragma unroll
            for (int m = 0; m < NMIX; m++) { e[m] = __expf(z[m] - mx); sum += e[m]; }
            float inv = 1.f / sum;
#pragma unroll
            for (int m = 0; m < NMIX; m++) sh_sm[b][s][c][m] = e[m] * inv;
        }
        __syncthreads();

        if (tid < NB * NCH * NMIX) {              // mean over samples
            int b = tid / (NCH * NMIX);
            int cm = tid % (NCH * NMIX);
            int c = cm / NMIX, m = cm % NMIX;
            float s = 0.f;
#pragma unroll
            for (int ss = 0; ss < NS; ss++) s += sh_sm[b][ss][c][m];
            g_w[(b * NCH + c) * NMIX + m] = s * (1.0f / NS);
        }
        __syncthreads();
        if (tid == 0) { __threadfence(); atomicExch(&g_flag, 1); }
    }

    // ---- phase C: all blocks wait for weights, build pair-packed tables ----
    if (tid == 0) { while (atomicAdd(&g_flag, 0) == 0) {} __threadfence(); }
    __syncthreads();

    {
        int idx = blk * 256 + tid;                // 186*256 = 47616 = 24*1984
        int bc  = idx / TBLP;
        int k   = idx % TBLP;
        float d0 = (float)k * (1.0f / TSCALE);
        float d1 = (float)(k + 1) * (1.0f / TSCALE);
        float d20 = d0 * d0, d21 = d1 * d1;
        float a0 = 0.f, a1 = 0.f;
#pragma unroll
        for (int m = 0; m < NMIX; m++) {
            float iv = inv_std[m];
            float a  = -0.5f * PI2f * PI2f * iv * iv * LOG2E;
            float p  = PI2f * mu[m];
            float w  = g_w[bc * NMIX + m];
            a0 = fmaf(w, ex2f_(a * d20) * __cosf(p * d0), a0);
            a1 = fmaf(w, ex2f_(a * d21) * __cosf(p * d1), a1);
        }
        g_ftab2[bc][k] = make_float2(a0, a1);
    }
}

// ---------------------------------------------------------------------------
// Kernel 3: output via shared pair-packed LUT. block = (b, i-tile 16).
// 192 threads; each thread owns 4 consecutive j (full 768 row per block).
// Per (i,thread): 12 LDS.64 lookups + 3 STG.128 stores (48B contiguous).
// ---------------------------------------------------------------------------
__global__ void __launch_bounds__(OJT) out_kernel(
    const float* __restrict__ xc, float* __restrict__ out)
{
    int bid = blockIdx.x;
    int it  = bid % (ND / OIT);
    int b   = bid / (ND / OIT);
    int tid = threadIdx.x;

    __shared__ float2 fs2[NCH * TBLP];    // 47616 B
    __shared__ float xish[OIT * NCH];
    __shared__ float dsh[NCH];

    {
        const float4* src = (const float4*)&g_ftab2[b * NCH][0];
        float4* dst = (float4*)fs2;
        for (int q = tid; q < NCH * TBLP / 2; q += OJT) dst[q] = src[q];
    }
    int ibase = it * OIT;
    if (tid < OIT * NCH)
        xish[tid] = xc[(b * ND + ibase) * NCH + tid];
    if (tid < NCH) dsh[tid] = g_diag[tid];

    int j0 = tid * 4;
    float xj[4][NCH];
    {
        const float4* xp = (const float4*)&xc[(b * ND + j0) * NCH];
        float4 v0 = xp[0], v1 = xp[1], v2 = xp[2];
        xj[0][0] = v0.x; xj[0][1] = v0.y; xj[0][2] = v0.z;
        xj[1][0] = v0.w; xj[1][1] = v1.x; xj[1][2] = v1.y;
        xj[2][0] = v1.z; xj[2][1] = v1.w; xj[2][2] = v2.x;
        xj[3][0] = v2.y; xj[3][1] = v2.z; xj[3][2] = v2.w;
    }
    __syncthreads();

    float dg0 = dsh[0], dg1 = dsh[1], dg2 = dsh[2];

    for (int ii = 0; ii < OIT; ii++) {
        int i = ibase + ii;
        float xi0 = xish[ii * NCH + 0];
        float xi1 = xish[ii * NCH + 1];
        float xi2 = xish[ii * NCH + 2];
        float rr[4][NCH];
#pragma unroll
        for (int jj = 0; jj < 4; jj++) {
            float t0 = fminf(fabsf(xi0 - xj[jj][0]) * TSCALE, TCLAMP);
            float t1 = fminf(fabsf(xi1 - xj[jj][1]) * TSCALE, TCLAMP);
            float t2 = fminf(fabsf(xi2 - xj[jj][2]) * TSCALE, TCLAMP);
            int k0 = (int)t0, k1 = (int)t1, k2 = (int)t2;
            float fr0 = t0 - (float)k0, fr1 = t1 - (float)k1, fr2 = t2 - (float)k2;
            float2 p0 = fs2[0 * TBLP + k0];
            float2 p1 = fs2[1 * TBLP + k1];
            float2 p2 = fs2[2 * TBLP + k2];
            rr[jj][0] = fmaf(fr0, p0.y - p0.x, p0.x);
            rr[jj][1] = fmaf(fr1, p1.y - p1.x, p1.x);
            rr[jj][2] = fmaf(fr2, p2.y - p2.x, p2.x);
        }
        int dj = i - j0;
        if ((unsigned)dj < 4u) {
            rr[dj][0] += dg0; rr[dj][1] += dg1; rr[dj][2] += dg2;
        }
        float4* op = (float4*)(out + ((size_t)(b * ND + i) * ND + j0) * NCH);
        op[0] = make_float4(rr[0][0], rr[0][1], rr[0][2], rr[1][0]);
        op[1] = make_float4(rr[1][1], rr[1][2], rr[2][0], rr[2][1]);
        op[2] = make_float4(rr[2][2], rr[3][0], rr[3][1], rr[3][2]);
    }
}

extern "C" void kernel_launch(void* const* d_in, const int* in_sizes, int n_in,
                              void* d_out, int out_size)
{
    const float* xc      = (const float*)d_in[0];
    const float* yc      = (const float*)d_in[1];
    const float* mu      = (const float*)d_in[2];
    const float* inv_std = (const float*)d_in[3];
    const float* likerr  = (const float*)d_in[4];
    const float* unif    = (const float*)d_in[5];
    const float* W1 = (const float*)d_in[6];  const float* b1 = (const float*)d_in[7];
    const float* W2 = (const float*)d_in[8];  const float* b2 = (const float*)d_in[9];
    const float* W3 = (const float*)d_in[10]; const float* b3 = (const float*)d_in[11];
    const float* W4 = (const float*)d_in[12]; const float* b4 = (const float*)d_in[13];
    const float* W5 = (const float*)d_in[14]; const float* b5 = (const float*)d_in[15];

    feat_kernel<<<NB * NCH * NI_T * NJC, 128>>>(xc, yc, mu, inv_std);
    fused_mid_kernel<<<FUSED_BLOCKS, 256>>>(yc, W1, b1, likerr, unif,
                                            W2, b2, W3, b3, W4, b4, W5, b5,
                                            mu, inv_std);
    out_kernel<<<NB * (ND / OIT), OJT>>>(xc, (float*)d_out);
}

// round 9
// speedup vs baseline: 1.0374x; 1.0374x over previous
#include <cuda_runtime.h>
#include <math.h>

#define NB   8
#define ND   768
#define NCH  3
#define NMIX 5
#define H    10
#define NS   10
#define PI2f 6.283185307179586f
#define ZITTERf 1e-4f
#define INV_TEMP 10.0f
#define LOG2E 1.44269504088896341f

#define NJC 16              // j-chunks in feat
#define JC  48              // ND/NJC
#define ITILE 256           // i-range per feat block (2 i per thread)
#define NI_T  3             // ND/ITILE
#define NT2   3             // feat2 i-tiles of 256
#define JT  256             // j-tile in out kernel (== blockDim)
#define IT  48              // i-tile in out kernel (ND/IT = 16)

#define TBLP   1984         // float2 pair-entries per (b,c); 3*TBLP*8 = 47616B shared
#define TSCALE 220.0f       // entries per unit |d| (covers |d| <= 9.0)
#define TCLAMP 1982.0f
#define OUT_BLOCKS (NB * (ND / JT) * (ND / IT))   // 384
#define ENT_PER_BLK (NB * NCH * TBLP / OUT_BLOCKS) // 124
#define FEAT2_BLOCKS (NB * NCH * NT2)              // 72

// cross-kernel scratch (__device__ globals per allocation rules)
__device__ float g_facc[NB * NCH][NJC][NMIX][ND];   // feat partials, coalesced in i
__device__ float g_hpart[NB * NCH][NT2][H];
__device__ float g_w[NB * NCH * NMIX];
__device__ float g_diag[NCH];
__device__ __align__(16) float2 g_ftab2[NB * NCH][TBLP];
__device__ int g_cnt;
__device__ int g_flag;
__device__ int g_cnt2;

__device__ __forceinline__ float ex2f_(float x) {
    float y; asm("ex2.approx.f32 %0, %1;" : "=f"(y) : "f"(x)); return y;
}

// ---------------------------------------------------------------------------
// Kernel 1: pairwise SM-kernel j-reduction with split accumulators.
// block = (b, c, i-tile 256, j-chunk 48); 128 threads, 2 i's per thread.
// Also resets the fused sync words (runs first every launch).
// ---------------------------------------------------------------------------
__global__ void __launch_bounds__(128) feat_kernel(
    const float* __restrict__ xc, const float* __restrict__ yc,
    const float* __restrict__ mu, const float* __restrict__ inv_std)
{
    if (blockIdx.x == 0 && threadIdx.x == 0) { g_cnt = 0; g_flag = 0; g_cnt2 = 0; }

    int bid   = blockIdx.x;
    int chunk = bid % NJC;
    int r     = bid / NJC;
    int tile  = r % NI_T;
    int bc    = r / NI_T;
    int c     = bc % NCH;
    int b     = bc / NCH;
    int tid   = threadIdx.x;

    __shared__ float4 jt[JC][3];

    float km2[NMIX], pm[NMIX];
#pragma unroll
    for (int m = 0; m < NMIX; m++) {
        float iv = inv_std[m];
        km2[m] = -0.5f * PI2f * PI2f * iv * iv * LOG2E;
        pm[m]  = PI2f * mu[m];
    }

    int j0 = chunk * JC;
    if (tid < JC) {
        float xv = xc[(b * ND + j0 + tid) * NCH + c];
        float yv = yc[(b * ND + j0 + tid) * NCH + c];
        float cy[NMIX], sy[NMIX];
#pragma unroll
        for (int m = 0; m < NMIX; m++) {
            float s, co;
            __sincosf(pm[m] * xv, &s, &co);
            cy[m] = co * yv;
            sy[m] = s * yv;
        }
        jt[tid][0] = make_float4(cy[0], cy[1], cy[2], cy[3]);
        jt[tid][1] = make_float4(cy[4], sy[0], sy[1], sy[2]);
        jt[tid][2] = make_float4(sy[3], sy[4], xv, 0.f);
    }

    int i0 = tile * ITILE + tid;
    int i1 = i0 + 128;
    float xi0 = xc[(b * ND + i0) * NCH + c];
    float xi1 = xc[(b * ND + i1) * NCH + c];

    float A0[NMIX], B0[NMIX], A1[NMIX], B1[NMIX];
#pragma unroll
    for (int m = 0; m < NMIX; m++) { A0[m] = B0[m] = A1[m] = B1[m] = 0.f; }
    __syncthreads();

#pragma unroll 2
    for (int j = 0; j < JC; j++) {
        float4 t0 = jt[j][0];
        float4 t1 = jt[j][1];
        float4 t2 = jt[j][2];
        float cy[NMIX] = {t0.x, t0.y, t0.z, t0.w, t1.x};
        float sy[NMIX] = {t1.y, t1.z, t1.w, t2.x, t2.y};
        float xj = t2.z;
        float d0 = xi0 - xj, d20 = d0 * d0;
        float d1 = xi1 - xj, d21 = d1 * d1;
#pragma unroll
        for (int m = 0; m < NMIX; m++) {
            float e0 = ex2f_(km2[m] * d20);
            float e1 = ex2f_(km2[m] * d21);
            A0[m] = fmaf(e0, cy[m], A0[m]);
            B0[m] = fmaf(e0, sy[m], B0[m]);
            A1[m] = fmaf(e1, cy[m], A1[m]);
            B1[m] = fmaf(e1, sy[m], B1[m]);
        }
    }

    // apply i-side rotation once per (i,m)
#pragma unroll
    for (int m = 0; m < NMIX; m++) {
        float s0, c0, s1, c1;
        __sincosf(pm[m] * xi0, &s0, &c0);
        __sincosf(pm[m] * xi1, &s1, &c1);
        g_facc[bc][chunk][m][i0] = fmaf(c0, A0[m], s0 * B0[m]);
        g_facc[bc][chunk][m][i1] = fmaf(c1, A1[m], s1 * B1[m]);
    }
}

// ---------------------------------------------------------------------------
// Kernel 2 (fully fused): feat2 -> MLP/Gumbel -> distributed table build ->
// LUT output. All 384 blocks are co-resident (48KB smem -> 4 blocks/SM),
// so the device-side spin barriers cannot deadlock.
// ---------------------------------------------------------------------------
__global__ void __launch_bounds__(256) out_kernel(
    const float* __restrict__ xc, float* __restrict__ out,
    const float* __restrict__ yc,
    const float* __restrict__ W1, const float* __restrict__ b1,
    const float* __restrict__ likerr, const float* __restrict__ unif,
    const float* __restrict__ W2, const float* __restrict__ b2,
    const float* __restrict__ W3, const float* __restrict__ b3,
    const float* __restrict__ W4, const float* __restrict__ b4,
    const float* __restrict__ W5, const float* __restrict__ b5,
    const float* __restrict__ mu, const float* __restrict__ inv_std)
{
    int blk = blockIdx.x;
    int tid = threadIdx.x;

    __shared__ float2 fs2[NCH * TBLP];    // 47616 B (reused: feat2 scratch first)
    __shared__ float xish[IT * NCH];
    __shared__ float dsh[NCH];

    // ---- phase A: feat2 (layer-1 + partial i-reduction) on blocks 0..71 ----
    if (blk < FEAT2_BLOCKS) {
        float* sh_h = (float*)fs2;        // 256*H floats = 10240B < 47616B
        int tile = blk % NT2;
        int bc   = blk / NT2;
        int c    = bc % NCH;
        int b    = bc / NCH;
        int i    = tile * 256 + tid;

        float yi = yc[(b * ND + i) * NCH + c];
        float tif[NMIX + 1];
#pragma unroll
        for (int m = 0; m < NMIX; m++) {
            float s = 0.f;
#pragma unroll
            for (int ch = 0; ch < NJC; ch++) s += g_facc[bc][ch][m][i];
            tif[m] = s + ZITTERf * yi;
        }
        tif[NMIX] = yi;

#pragma unroll
        for (int k = 0; k < H; k++) {
            float s = b1[k];
#pragma unroll
            for (int t = 0; t < NMIX + 1; t++) s = fmaf(W1[k * (NMIX + 1) + t], tif[t], s);
            sh_h[tid * H + k] = fmaxf(s, 0.f);
        }
        __syncthreads();

        if (tid < H) {
            float s = 0.f;
            for (int t = 0; t < 256; t++) s += sh_h[t * H + tid];
            g_hpart[bc][tile][tid] = s;
        }
        __syncthreads();
        if (tid == 0) { __threadfence(); atomicAdd(&g_cnt, 1); }
    }

    // ---- phase B: block 0 waits for all feat2 blocks, runs the MLP ----
    if (blk == 0) {
        if (tid == 0) { while (atomicAdd(&g_cnt, 0) < FEAT2_BLOCKS) {} __threadfence(); }
        __syncthreads();

        __shared__ float sh_h0[NB][NCH * H];
        __shared__ float sh_a[NB][H];
        __shared__ float sh_b[NB][H];
        __shared__ float sh_ll[NB][NCH * NMIX];
        __shared__ float sh_sm[NB][NS][NCH][NMIX];

        if (tid < NB * NCH) {
            int b = tid / NCH, c = tid % NCH;
            for (int k = 0; k < H; k++) {
                float s = 0.f;
#pragma unroll
                for (int tt = 0; tt < NT2; tt++) s += g_hpart[b * NCH + c][tt][k];
                sh_h0[b][c * H + k] = s * (1.0f / ND);
            }
        }
        if (tid < NCH) {
            float l = fminf(fmaxf(likerr[tid], 0.1f), 1.0f);
            g_diag[tid] = ZITTERf + l * l;
        }
        __syncthreads();

        if (tid < NB * H) {                       // layer 2
            int b = tid / H, k = tid % H;
            float s = b2[k];
            for (int u = 0; u < NCH * H; u++) s = fmaf(W2[k * (NCH * H) + u], sh_h0[b][u], s);
            sh_a[b][k] = fmaxf(s, 0.f);
        }
        __syncthreads();
        if (tid < NB * H) {                       // layer 3
            int b = tid / H, k = tid % H;
            float s = b3[k];
            for (int u = 0; u < H; u++) s = fmaf(W3[k * H + u], sh_a[b][u], s);
            sh_b[b][k] = fmaxf(s, 0.f);
        }
        __syncthreads();
        if (tid < NB * H) {                       // layer 4
            int b = tid / H, k = tid % H;
            float s = b4[k];
            for (int u = 0; u < H; u++) s = fmaf(W4[k * H + u], sh_b[b][u], s);
            sh_a[b][k] = fmaxf(s, 0.f);
        }
        __syncthreads();
        if (tid < NB * NCH * NMIX) {              // layer 5 -> logits
            int b = tid / (NCH * NMIX), n = tid % (NCH * NMIX);
            float s = b5[n];
            for (int u = 0; u < H; u++) s = fmaf(W5[n * H + u], sh_a[b][u], s);
            sh_ll[b][n] = s;
        }
        __syncthreads();

        if (tid < NB * NS * NCH) {                // gumbel softmax per (b,s,c)
            int b = tid / (NS * NCH);
            int rem = tid % (NS * NCH);
            int s = rem / NCH, c = rem % NCH;
            float z[NMIX], mx = -1e30f;
#pragma unroll
            for (int m = 0; m < NMIX; m++) {
                float u = unif[((b * NS + s) * NCH + c) * NMIX + m];
                float g = -__logf(-__logf(u + 1e-20f));
                z[m] = (g + sh_ll[b][c * NMIX + m]) * INV_TEMP;
                mx = fmaxf(mx, z[m]);
            }
            float sum = 0.f, e[NMIX];
#pragma unroll
            for (int m = 0; m < NMIX; m++) { e[m] = __expf(z[m] - mx); sum += e[m]; }
            float inv = 1.f / sum;
#pragma unroll
            for (int m = 0; m < NMIX; m++) sh_sm[b][s][c][m] = e[m] * inv;
        }
        __syncthreads();

        if (tid < NB * NCH * NMIX) {              // mean over samples
            int b = tid / (NCH * NMIX);
            int cm = tid % (NCH * NMIX);
            int c = cm / NMIX, m = cm % NMIX;
            float s = 0.f;
#pragma unroll
            for (int ss = 0; ss < NS; ss++) s += sh_sm[b][ss][c][m];
            g_w[(b * NCH + c) * NMIX + m] = s * (1.0f / NS);
        }
        __syncthreads();
        if (tid == 0) { __threadfence(); atomicExch(&g_flag, 1); }
    }

    // ---- phase C: all blocks wait for weights, build 124 table entries each ----
    if (tid == 0) { while (atomicAdd(&g_flag, 0) == 0) {} __threadfence(); }
    __syncthreads();

    if (tid < ENT_PER_BLK) {
        int idx = blk * ENT_PER_BLK + tid;        // 384*124 = 47616 = 24*1984
        int bc  = idx / TBLP;
        int k   = idx % TBLP;
        float d0 = (float)k * (1.0f / TSCALE);
        float d1 = (float)(k + 1) * (1.0f / TSCALE);
        float d20 = d0 * d0, d21 = d1 * d1;
        float a0 = 0.f, a1 = 0.f;
#pragma unroll
        for (int m = 0; m < NMIX; m++) {
            float iv = inv_std[m];
            float a  = -0.5f * PI2f * PI2f * iv * iv * LOG2E;
            float p  = PI2f * mu[m];
            float w  = g_w[bc * NMIX + m];
            a0 = fmaf(w, ex2f_(a * d20) * __cosf(p * d0), a0);
            a1 = fmaf(w, ex2f_(a * d21) * __cosf(p * d1), a1);
        }
        g_ftab2[bc][k] = make_float2(a0, a1);
    }
    __syncthreads();
    if (tid == 0) { __threadfence(); atomicAdd(&g_cnt2, 1); }

    // ---- phase D: wait for full table, copy to shared, run LUT output ----
    if (tid == 0) { while (atomicAdd(&g_cnt2, 0) < OUT_BLOCKS) {} __threadfence(); }
    __syncthreads();

    int it  = blk % (ND / IT);
    int r   = blk / (ND / IT);
    int jt  = r % (ND / JT);
    int b   = r / (ND / JT);

    {
        const float4* src = (const float4*)&g_ftab2[b * NCH][0];
        float4* dst = (float4*)fs2;
        for (int q = tid; q < NCH * TBLP / 2; q += 256) dst[q] = src[q];
    }
    int ibase = it * IT;
    for (int q = tid; q < IT * NCH; q += 256)
        xish[q] = xc[(b * ND + ibase) * NCH + q];
    if (tid < NCH) dsh[tid] = g_diag[tid];

    int j = jt * JT + tid;
    float xj0 = xc[(b * ND + j) * NCH + 0];
    float xj1 = xc[(b * ND + j) * NCH + 1];
    float xj2 = xc[(b * ND + j) * NCH + 2];
    __syncthreads();

    float dg0 = dsh[0], dg1 = dsh[1], dg2 = dsh[2];

    float* o = out + ((size_t)(b * ND + ibase) * ND + j) * NCH;

    for (int ii = 0; ii < IT; ii++) {
        int i = ibase + ii;
        float t0 = fminf(fabsf(xish[ii * NCH + 0] - xj0) * TSCALE, TCLAMP);
        float t1 = fminf(fabsf(xish[ii * NCH + 1] - xj1) * TSCALE, TCLAMP);
        float t2 = fminf(fabsf(xish[ii * NCH + 2] - xj2) * TSCALE, TCLAMP);
        int k0 = (int)t0, k1 = (int)t1, k2 = (int)t2;
        float fr0 = t0 - (float)k0, fr1 = t1 - (float)k1, fr2 = t2 - (float)k2;
        float2 p0 = fs2[0 * TBLP + k0];
        float2 p1 = fs2[1 * TBLP + k1];
        float2 p2 = fs2[2 * TBLP + k2];
        float r0 = fmaf(fr0, p0.y - p0.x, p0.x);
        float r1 = fmaf(fr1, p1.y - p1.x, p1.x);
        float r2 = fmaf(fr2, p2.y - p2.x, p2.x);
        if (i == j) { r0 += dg0; r1 += dg1; r2 += dg2; }
        o[0] = r0; o[1] = r1; o[2] = r2;
        o += (size_t)ND * NCH;
    }
}

extern "C" void kernel_launch(void* const* d_in, const int* in_sizes, int n_in,
                              void* d_out, int out_size)
{
    const float* xc      = (const float*)d_in[0];
    const float* yc      = (const float*)d_in[1];
    const float* mu      = (const float*)d_in[2];
    const float* inv_std = (const float*)d_in[3];
    const float* likerr  = (const float*)d_in[4];
    const float* unif    = (const float*)d_in[5];
    const float* W1 = (const float*)d_in[6];  const float* b1 = (const float*)d_in[7];
    const float* W2 = (const float*)d_in[8];  const float* b2 = (const float*)d_in[9];
    const float* W3 = (const float*)d_in[10]; const float* b3 = (const float*)d_in[11];
    const float* W4 = (const float*)d_in[12]; const float* b4 = (const float*)d_in[13];
    const float* W5 = (const float*)d_in[14]; const float* b5 = (const float*)d_in[15];

    feat_kernel<<<NB * NCH * NI_T * NJC, 128>>>(xc, yc, mu, inv_std);
    out_kernel<<<OUT_BLOCKS, 256>>>(xc, (float*)d_out, yc, W1, b1, likerr, unif,
                                    W2, b2, W3, b3, W4, b4, W5, b5, mu, inv_std);
}

// round 10
// speedup vs baseline: 1.0598x; 1.0216x over previous
#include <cuda_runtime.h>
#include <math.h>

#define NB   8
#define ND   768
#define NCH  3
#define NMIX 5
#define H    10
#define NS   10
#define PI2f 6.283185307179586f
#define ZITTERf 1e-4f
#define INV_TEMP 10.0f
#define LOG2E 1.44269504088896341f

#define NJC 16              // j-chunks in feat
#define JC  48              // ND/NJC
#define ITILE 256           // i-range per feat block (2 i per thread)
#define NI_T  3             // ND/ITILE
#define NT2   3             // feat2 i-tiles of 256
#define JT  256             // j-tile in out phase (== blockDim)
#define IT  32              // i-tile in out phase (ND/IT = 24)

#define TBLP   1984         // float2 pair-entries per (b,c); 3*TBLP*8 = 47616B shared
#define TSCALE 220.0f       // entries per unit |d| (covers |d| <= 9.0)
#define TCLAMP 1982.0f
#define OUT_BLOCKS (NB * (ND / JT) * (ND / IT))   // 576
#define BUILD_BLOCKS 186                           // 186*256 = 47616 entries
#define FEAT2_BLOCKS (NB * NCH * NT2)              // 72

// cross-kernel scratch (__device__ globals per allocation rules)
__device__ float g_facc[NB * NCH][NJC][NMIX][ND];   // feat partials, coalesced in i
__device__ float g_hpart[NB * NCH][NT2][H];
__device__ float g_w[NB * NCH * NMIX];
__device__ float g_diag[NCH];
__device__ __align__(16) float2 g_ftab2[NB * NCH][TBLP];
__device__ int g_cnt;
__device__ int g_flag;
__device__ int g_cnt2;

__device__ __forceinline__ float ex2f_(float x) {
    float y; asm("ex2.approx.f32 %0, %1;" : "=f"(y) : "f"(x)); return y;
}

// ---------------------------------------------------------------------------
// Kernel 1: pairwise SM-kernel j-reduction with split accumulators.
// block = (b, c, i-tile 256, j-chunk 48); 128 threads, 2 i's per thread.
// Also resets the fused sync words (runs first every launch).
// ---------------------------------------------------------------------------
__global__ void __launch_bounds__(128) feat_kernel(
    const float* __restrict__ xc, const float* __restrict__ yc,
    const float* __restrict__ mu, const float* __restrict__ inv_std)
{
    if (blockIdx.x == 0 && threadIdx.x == 0) { g_cnt = 0; g_flag = 0; g_cnt2 = 0; }

    int bid   = blockIdx.x;
    int chunk = bid % NJC;
    int r     = bid / NJC;
    int tile  = r % NI_T;
    int bc    = r / NI_T;
    int c     = bc % NCH;
    int b     = bc / NCH;
    int tid   = threadIdx.x;

    __shared__ float4 jt[JC][3];

    float km2[NMIX], pm[NMIX];
#pragma unroll
    for (int m = 0; m < NMIX; m++) {
        float iv = inv_std[m];
        km2[m] = -0.5f * PI2f * PI2f * iv * iv * LOG2E;
        pm[m]  = PI2f * mu[m];
    }

    int j0 = chunk * JC;
    if (tid < JC) {
        float xv = xc[(b * ND + j0 + tid) * NCH + c];
        float yv = yc[(b * ND + j0 + tid) * NCH + c];
        float cy[NMIX], sy[NMIX];
#pragma unroll
        for (int m = 0; m < NMIX; m++) {
            float s, co;
            __sincosf(pm[m] * xv, &s, &co);
            cy[m] = co * yv;
            sy[m] = s * yv;
        }
        jt[tid][0] = make_float4(cy[0], cy[1], cy[2], cy[3]);
        jt[tid][1] = make_float4(cy[4], sy[0], sy[1], sy[2]);
        jt[tid][2] = make_float4(sy[3], sy[4], xv, 0.f);
    }

    int i0 = tile * ITILE + tid;
    int i1 = i0 + 128;
    float xi0 = xc[(b * ND + i0) * NCH + c];
    float xi1 = xc[(b * ND + i1) * NCH + c];

    float A0[NMIX], B0[NMIX], A1[NMIX], B1[NMIX];
#pragma unroll
    for (int m = 0; m < NMIX; m++) { A0[m] = B0[m] = A1[m] = B1[m] = 0.f; }
    __syncthreads();

#pragma unroll 2
    for (int j = 0; j < JC; j++) {
        float4 t0 = jt[j][0];
        float4 t1 = jt[j][1];
        float4 t2 = jt[j][2];
        float cy[NMIX] = {t0.x, t0.y, t0.z, t0.w, t1.x};
        float sy[NMIX] = {t1.y, t1.z, t1.w, t2.x, t2.y};
        float xj = t2.z;
        float d0 = xi0 - xj, d20 = d0 * d0;
        float d1 = xi1 - xj, d21 = d1 * d1;
#pragma unroll
        for (int m = 0; m < NMIX; m++) {
            float e0 = ex2f_(km2[m] * d20);
            float e1 = ex2f_(km2[m] * d21);
            A0[m] = fmaf(e0, cy[m], A0[m]);
            B0[m] = fmaf(e0, sy[m], B0[m]);
            A1[m] = fmaf(e1, cy[m], A1[m]);
            B1[m] = fmaf(e1, sy[m], B1[m]);
        }
    }

    // apply i-side rotation once per (i,m)
#pragma unroll
    for (int m = 0; m < NMIX; m++) {
        float s0, c0, s1, c1;
        __sincosf(pm[m] * xi0, &s0, &c0);
        __sincosf(pm[m] * xi1, &s1, &c1);
        g_facc[bc][chunk][m][i0] = fmaf(c0, A0[m], s0 * B0[m]);
        g_facc[bc][chunk][m][i1] = fmaf(c1, A1[m], s1 * B1[m]);
    }
}

// ---------------------------------------------------------------------------
// Kernel 2 (fully fused): feat2 -> MLP/Gumbel -> distributed table build ->
// LUT output. Grid 576, 256 threads, 4 blocks/SM (576 <= 592 resident), so
// the device-side spin barriers cannot deadlock.
// ---------------------------------------------------------------------------
__global__ void __launch_bounds__(256, 4) out_kernel(
    const float* __restrict__ xc, float* __restrict__ out,
    const float* __restrict__ yc,
    const float* __restrict__ W1, const float* __restrict__ b1,
    const float* __restrict__ likerr, const float* __restrict__ unif,
    const float* __restrict__ W2, const float* __restrict__ b2,
    const float* __restrict__ W3, const float* __restrict__ b3,
    const float* __restrict__ W4, const float* __restrict__ b4,
    const float* __restrict__ W5, const float* __restrict__ b5,
    const float* __restrict__ mu, const float* __restrict__ inv_std)
{
    int blk = blockIdx.x;
    int tid = threadIdx.x;

    __shared__ float2 fs2[NCH * TBLP];    // 47616 B (reused: feat2 scratch first)
    __shared__ float xish[IT * NCH];

    // ---- out-phase tile indices; hoist xc loads before the barriers ----
    int itile = blk % (ND / IT);
    int rr_   = blk / (ND / IT);
    int jt    = rr_ % (ND / JT);
    int ob    = rr_ / (ND / JT);
    int ibase = itile * IT;
    int j     = jt * JT + tid;
    float xj0 = xc[((size_t)ob * ND + j) * NCH + 0];
    float xj1 = xc[((size_t)ob * ND + j) * NCH + 1];
    float xj2 = xc[((size_t)ob * ND + j) * NCH + 2];
    if (tid < IT * NCH)
        xish[tid] = xc[((size_t)ob * ND + ibase) * NCH + tid];

    // ---- phase A: feat2 (layer-1 + partial i-reduction) on blocks 0..71 ----
    if (blk < FEAT2_BLOCKS) {
        float* sh_h = (float*)fs2;        // 256*H floats = 10240B < 47616B
        int tile = blk % NT2;
        int bc   = blk / NT2;
        int c    = bc % NCH;
        int b    = bc / NCH;
        int i    = tile * 256 + tid;

        float yi = yc[(b * ND + i) * NCH + c];
        float tif[NMIX + 1];
#pragma unroll
        for (int m = 0; m < NMIX; m++) {
            float s = 0.f;
#pragma unroll
            for (int ch = 0; ch < NJC; ch++) s += g_facc[bc][ch][m][i];
            tif[m] = s + ZITTERf * yi;
        }
        tif[NMIX] = yi;

#pragma unroll
        for (int k = 0; k < H; k++) {
            float s = b1[k];
#pragma unroll
            for (int t = 0; t < NMIX + 1; t++) s = fmaf(W1[k * (NMIX + 1) + t], tif[t], s);
            sh_h[tid * H + k] = fmaxf(s, 0.f);
        }
        __syncthreads();

        if (tid < H) {
            float s = 0.f;
            for (int t = 0; t < 256; t++) s += sh_h[t * H + tid];
            g_hpart[bc][tile][tid] = s;
        }
        __syncthreads();
        if (tid == 0) { __threadfence(); atomicAdd(&g_cnt, 1); }
    }

    // ---- phase B: block 0 waits for all feat2 blocks, runs the MLP ----
    if (blk == 0) {
        if (tid == 0) { while (atomicAdd(&g_cnt, 0) < FEAT2_BLOCKS) { __nanosleep(64); } __threadfence(); }
        __syncthreads();

        __shared__ float sh_h0[NB][NCH * H];
        __shared__ float sh_a[NB][H];
        __shared__ float sh_b[NB][H];
        __shared__ float sh_ll[NB][NCH * NMIX];
        __shared__ float sh_sm[NB][NS][NCH][NMIX];

        if (tid < NB * NCH) {
            int b = tid / NCH, c = tid % NCH;
            for (int k = 0; k < H; k++) {
                float s = 0.f;
#pragma unroll
                for (int tt = 0; tt < NT2; tt++) s += g_hpart[b * NCH + c][tt][k];
                sh_h0[b][c * H + k] = s * (1.0f / ND);
            }
        }
        if (tid < NCH) {
            float l = fminf(fmaxf(likerr[tid], 0.1f), 1.0f);
            g_diag[tid] = ZITTERf + l * l;
        }
        __syncthreads();

        if (tid < NB * H) {                       // layer 2
            int b = tid / H, k = tid % H;
            float s = b2[k];
            for (int u = 0; u < NCH * H; u++) s = fmaf(W2[k * (NCH * H) + u], sh_h0[b][u], s);
            sh_a[b][k] = fmaxf(s, 0.f);
        }
        __syncthreads();
        if (tid < NB * H) {                       // layer 3
            int b = tid / H, k = tid % H;
            float s = b3[k];
            for (int u = 0; u < H; u++) s = fmaf(W3[k * H + u], sh_a[b][u], s);
            sh_b[b][k] = fmaxf(s, 0.f);
        }
        __syncthreads();
        if (tid < NB * H) {                       // layer 4
            int b = tid / H, k = tid % H;
            float s = b4[k];
            for (int u = 0; u < H; u++) s = fmaf(W4[k * H + u], sh_b[b][u], s);
            sh_a[b][k] = fmaxf(s, 0.f);
        }
        __syncthreads();
        if (tid < NB * NCH * NMIX) {              // layer 5 -> logits
            int b = tid / (NCH * NMIX), n = tid % (NCH * NMIX);
            float s = b5[n];
            for (int u = 0; u < H; u++) s = fmaf(W5[n * H + u], sh_a[b][u], s);
            sh_ll[b][n] = s;
        }
        __syncthreads();

        if (tid < NB * NS * NCH) {                // gumbel softmax per (b,s,c)
            int b = tid / (NS * NCH);
            int rem = tid % (NS * NCH);
            int s = rem / NCH, c = rem % NCH;
            float z[NMIX], mx = -1e30f;
#pragma unroll
            for (int m = 0; m < NMIX; m++) {
                float u = unif[((b * NS + s) * NCH + c) * NMIX + m];
                float g = -__logf(-__logf(u + 1e-20f));
                z[m] = (g + sh_ll[b][c * NMIX + m]) * INV_TEMP;
                mx = fmaxf(mx, z[m]);
            }
            float sum = 0.f, e[NMIX];
#pragma unroll
            for (int m = 0; m < NMIX; m++) { e[m] = __expf(z[m] - mx); sum += e[m]; }
            float inv = 1.f / sum;
#pragma unroll
            for (int m = 0; m < NMIX; m++) sh_sm[b][s][c][m] = e[m] * inv;
        }
        __syncthreads();

        if (tid < NB * NCH * NMIX) {              // mean over samples
            int b = tid / (NCH * NMIX);
            int cm = tid % (NCH * NMIX);
            int c = cm / NMIX, m = cm % NMIX;
            float s = 0.f;
#pragma unroll
            for (int ss = 0; ss < NS; ss++) s += sh_sm[b][ss][c][m];
            g_w[(b * NCH + c) * NMIX + m] = s * (1.0f / NS);
        }
        __syncthreads();
        if (tid == 0) { __threadfence(); atomicExch(&g_flag, 1); }
    }

    // ---- phase C: wait for weights; first 186 blocks build 256 entries each ----
    if (tid == 0) { while (atomicAdd(&g_flag, 0) == 0) { __nanosleep(128); } __threadfence(); }
    __syncthreads();

    if (blk < BUILD_BLOCKS) {
        int idx = blk * 256 + tid;                // 186*256 = 47616 = 24*1984
        int bc  = idx / TBLP;
        int k   = idx % TBLP;
        float d0 = (float)k * (1.0f / TSCALE);
        float d1 = (float)(k + 1) * (1.0f / TSCALE);
        float d20 = d0 * d0, d21 = d1 * d1;
        float a0 = 0.f, a1 = 0.f;
#pragma unroll
        for (int m = 0; m < NMIX; m++) {
            float iv = inv_std[m];
            float a  = -0.5f * PI2f * PI2f * iv * iv * LOG2E;
            float p  = PI2f * mu[m];
            float w  = g_w[bc * NMIX + m];
            a0 = fmaf(w, ex2f_(a * d20) * __cosf(p * d0), a0);
            a1 = fmaf(w, ex2f_(a * d21) * __cosf(p * d1), a1);
        }
        g_ftab2[bc][k] = make_float2(a0, a1);
        __syncthreads();
        if (tid == 0) { __threadfence(); atomicAdd(&g_cnt2, 1); }
    }

    // ---- phase D: wait for full table, copy to shared, run LUT output ----
    if (tid == 0) { while (atomicAdd(&g_cnt2, 0) < BUILD_BLOCKS) { __nanosleep(128); } __threadfence(); }
    __syncthreads();

    {
        const float4* src = (const float4*)&g_ftab2[ob * NCH][0];
        float4* dst = (float4*)fs2;
        for (int q = tid; q < NCH * TBLP / 2; q += 256) dst[q] = src[q];
    }
    float dg0 = g_diag[0], dg1 = g_diag[1], dg2 = g_diag[2];
    __syncthreads();

    float* o = out + (((size_t)ob * ND + ibase) * ND + j) * NCH;

#pragma unroll 1
    for (int ii = 0; ii < IT; ii += 2) {
        int iA = ibase + ii;
        int iB = iA + 1;
        float tA0 = fminf(fabsf(xish[ii * NCH + 0] - xj0) * TSCALE, TCLAMP);
        float tA1 = fminf(fabsf(xish[ii * NCH + 1] - xj1) * TSCALE, TCLAMP);
        float tA2 = fminf(fabsf(xish[ii * NCH + 2] - xj2) * TSCALE, TCLAMP);
        float tB0 = fminf(fabsf(xish[ii * NCH + 3] - xj0) * TSCALE, TCLAMP);
        float tB1 = fminf(fabsf(xish[ii * NCH + 4] - xj1) * TSCALE, TCLAMP);
        float tB2 = fminf(fabsf(xish[ii * NCH + 5] - xj2) * TSCALE, TCLAMP);
        int kA0 = (int)tA0, kA1 = (int)tA1, kA2 = (int)tA2;
        int kB0 = (int)tB0, kB1 = (int)tB1, kB2 = (int)tB2;
        float2 pA0 = fs2[0 * TBLP + kA0];
        float2 pA1 = fs2[1 * TBLP + kA1];
        float2 pA2 = fs2[2 * TBLP + kA2];
        float2 pB0 = fs2[0 * TBLP + kB0];
        float2 pB1 = fs2[1 * TBLP + kB1];
        float2 pB2 = fs2[2 * TBLP + kB2];
        float fA0 = tA0 - (float)kA0, fA1 = tA1 - (float)kA1, fA2 = tA2 - (float)kA2;
        float fB0 = tB0 - (float)kB0, fB1 = tB1 - (float)kB1, fB2 = tB2 - (float)kB2;
        float rA0 = fmaf(fA0, pA0.y - pA0.x, pA0.x);
        float rA1 = fmaf(fA1, pA1.y - pA1.x, pA1.x);
        float rA2 = fmaf(fA2, pA2.y - pA2.x, pA2.x);
        float rB0 = fmaf(fB0, pB0.y - pB0.x, pB0.x);
        float rB1 = fmaf(fB1, pB1.y - pB1.x, pB1.x);
        float rB2 = fmaf(fB2, pB2.y - pB2.x, pB2.x);
        if (iA == j) { rA0 += dg0; rA1 += dg1; rA2 += dg2; }
        if (iB == j) { rB0 += dg0; rB1 += dg1; rB2 += dg2; }
        o[0] = rA0; o[1] = rA1; o[2] = rA2;
        o += (size_t)ND * NCH;
        o[0] = rB0; o[1] = rB1; o[2] = rB2;
        o += (size_t)ND * NCH;
    }
}

extern "C" void kernel_launch(void* const* d_in, const int* in_sizes, int n_in,
                              void* d_out, int out_size)
{
    const float* xc      = (const float*)d_in[0];
    const float* yc      = (const float*)d_in[1];
    const float* mu      = (const float*)d_in[2];
    const float* inv_std = (const float*)d_in[3];
    const float* likerr  = (const float*)d_in[4];
    const float* unif    = (const float*)d_in[5];
    const float* W1 = (const float*)d_in[6];  const float* b1 = (const float*)d_in[7];
    const float* W2 = (const float*)d_in[8];  const float* b2 = (const float*)d_in[9];
    const float* W3 = (const float*)d_in[10]; const float* b3 = (const float*)d_in[11];
    const float* W4 = (const float*)d_in[12]; const float* b4 = (const float*)d_in[13];
    const float* W5 = (const float*)d_in[14]; const float* b5 = (const float*)d_in[15];

    feat_kernel<<<NB * NCH * NI_T * NJC, 128>>>(xc, yc, mu, inv_std);
    out_kernel<<<OUT_BLOCKS, 256>>>(xc, (float*)d_out, yc, W1, b1, likerr, unif,
                                    W2, b2, W3, b3, W4, b4, W5, b5, mu, inv_std);
}

// round 11
// speedup vs baseline: 1.0730x; 1.0125x over previous
#include <cuda_runtime.h>
#include <math.h>

#define NB   8
#define ND   768
#define NCH  3
#define NMIX 5
#define H    10
#define NS   10
#define PI2f 6.283185307179586f
#define ZITTERf 1e-4f
#define INV_TEMP 10.0f
#define LOG2E 1.44269504088896341f

#define NJC 16              // j-chunks in feat
#define JC  48              // ND/NJC
#define ITILE 256           // i-range per feat block (2 i per thread)
#define NI_T  3             // ND/ITILE
#define FEAT_BLOCKS (NB * NCH * NI_T * NJC)   // 1152
#define NT2   6             // feat2 i-tiles of 128
#define FEAT2_BLOCKS (NB * NCH * NT2)          // 144
#define BUILD_BLOCKS 372                       // 372*128 = 47616 entries

#define JT  256             // j-tile in out kernel (== blockDim)
#define IT  32              // i-tile in out kernel (ND/IT = 24)
#define OUT_BLOCKS (NB * (ND / JT) * (ND / IT))   // 576

#define TBLP   1984         // float2 pair-entries per (b,c); 3*TBLP*8 = 47616B shared
#define TSCALE 220.0f       // entries per unit |d| (covers |d| <= 9.0)
#define TCLAMP 1982.0f

// cross-kernel scratch (__device__ globals per allocation rules)
__device__ float g_facc[NB * NCH][NJC][NMIX][ND];   // feat partials, coalesced in i
__device__ float g_hpart[NB * NCH][NT2][H];
__device__ float g_w[NB * NCH * NMIX];
__device__ float g_diag[NCH];
__device__ __align__(16) float2 g_ftab2[NB * NCH][TBLP];
__device__ int g_c0;    // feat main-work completions (target 1152)
__device__ int g_c1;    // feat2 completions (target 144)
__device__ int g_flag;  // weights ready

__device__ __forceinline__ float ex2f_(float x) {
    float y; asm("ex2.approx.f32 %0, %1;" : "=f"(y) : "f"(x)); return y;
}

// ---------------------------------------------------------------------------
// Kernel 1: feat main (all 1152 blocks) -> tail phases on low-indexed blocks:
//   blocks 0..143  : feat2 (layer-1 + i-reduction) after all main work done
//   block  0       : MLP layers 2-5 + Gumbel weights + diag
//   blocks 0..371  : build the pair-packed lookup tables (128 entries each)
// All spinner blocks (0..371) are first-wave resident; regs capped via
// __launch_bounds__(128,8) so >= 1036 blocks co-resident -> no deadlock.
// Sync words are reset by out_kernel (which runs after), statics start at 0.
// ---------------------------------------------------------------------------
__global__ void __launch_bounds__(128, 8) feat_kernel(
    const float* __restrict__ xc, const float* __restrict__ yc,
    const float* __restrict__ mu, const float* __restrict__ inv_std,
    const float* __restrict__ W1, const float* __restrict__ b1,
    const float* __restrict__ likerr, const float* __restrict__ unif,
    const float* __restrict__ W2, const float* __restrict__ b2,
    const float* __restrict__ W3, const float* __restrict__ b3,
    const float* __restrict__ W4, const float* __restrict__ b4,
    const float* __restrict__ W5, const float* __restrict__ b5)
{
    int bid = blockIdx.x;
    int tid = threadIdx.x;

    __shared__ float4 jt[JC][3];                 // 2304 B (feat main)
    __shared__ float sh2[128 * H];               // 5120 B (feat2 reduction)
    __shared__ float sh_h0[NB][NCH * H];         // MLP scratch
    __shared__ float sh_a[NB][H];
    __shared__ float sh_b[NB][H];
    __shared__ float sh_ll[NB][NCH * NMIX];
    __shared__ float sh_sm[NB][NS][NCH][NMIX];

    // ================= main pairwise reduction =================
    {
        int chunk = bid % NJC;
        int r     = bid / NJC;
        int tile  = r % NI_T;
        int bc    = r / NI_T;
        int c     = bc % NCH;
        int b     = bc / NCH;

        float km2[NMIX], pm[NMIX];
#pragma unroll
        for (int m = 0; m < NMIX; m++) {
            float iv = inv_std[m];
            km2[m] = -0.5f * PI2f * PI2f * iv * iv * LOG2E;
            pm[m]  = PI2f * mu[m];
        }

        int j0 = chunk * JC;
        if (tid < JC) {
            float xv = xc[(b * ND + j0 + tid) * NCH + c];
            float yv = yc[(b * ND + j0 + tid) * NCH + c];
            float cy[NMIX], sy[NMIX];
#pragma unroll
            for (int m = 0; m < NMIX; m++) {
                float s, co;
                __sincosf(pm[m] * xv, &s, &co);
                cy[m] = co * yv;
                sy[m] = s * yv;
            }
            jt[tid][0] = make_float4(cy[0], cy[1], cy[2], cy[3]);
            jt[tid][1] = make_float4(cy[4], sy[0], sy[1], sy[2]);
            jt[tid][2] = make_float4(sy[3], sy[4], xv, 0.f);
        }

        int i0 = tile * ITILE + tid;
        int i1 = i0 + 128;
        float xi0 = xc[(b * ND + i0) * NCH + c];
        float xi1 = xc[(b * ND + i1) * NCH + c];

        float A0[NMIX], B0[NMIX], A1[NMIX], B1[NMIX];
#pragma unroll
        for (int m = 0; m < NMIX; m++) { A0[m] = B0[m] = A1[m] = B1[m] = 0.f; }
        __syncthreads();

#pragma unroll 2
        for (int j = 0; j < JC; j++) {
            float4 t0 = jt[j][0];
            float4 t1 = jt[j][1];
            float4 t2 = jt[j][2];
            float cy[NMIX] = {t0.x, t0.y, t0.z, t0.w, t1.x};
            float sy[NMIX] = {t1.y, t1.z, t1.w, t2.x, t2.y};
            float xj = t2.z;
            float d0 = xi0 - xj, d20 = d0 * d0;
            float d1 = xi1 - xj, d21 = d1 * d1;
#pragma unroll
            for (int m = 0; m < NMIX; m++) {
                float e0 = ex2f_(km2[m] * d20);
                float e1 = ex2f_(km2[m] * d21);
                A0[m] = fmaf(e0, cy[m], A0[m]);
                B0[m] = fmaf(e0, sy[m], B0[m]);
                A1[m] = fmaf(e1, cy[m], A1[m]);
                B1[m] = fmaf(e1, sy[m], B1[m]);
            }
        }

#pragma unroll
        for (int m = 0; m < NMIX; m++) {
            float s0, c0, s1, c1;
            __sincosf(pm[m] * xi0, &s0, &c0);
            __sincosf(pm[m] * xi1, &s1, &c1);
            g_facc[bc][chunk][m][i0] = fmaf(c0, A0[m], s0 * B0[m]);
            g_facc[bc][chunk][m][i1] = fmaf(c1, A1[m], s1 * B1[m]);
        }
    }
    __syncthreads();
    if (tid == 0) { __threadfence(); atomicAdd(&g_c0, 1); }

    if (bid >= BUILD_BLOCKS) return;   // high blocks exit, freeing slots

    // ================= phase A: feat2 on blocks 0..143 =================
    if (bid < FEAT2_BLOCKS) {
        if (tid == 0) {
            while (atomicAdd(&g_c0, 0) < FEAT_BLOCKS) { __nanosleep(64); }
            __threadfence();
        }
        __syncthreads();

        int tile = bid % NT2;
        int bc   = bid / NT2;
        int c    = bc % NCH;
        int b    = bc / NCH;
        int i    = tile * 128 + tid;

        float yi = yc[(b * ND + i) * NCH + c];
        float tif[NMIX + 1];
#pragma unroll
        for (int m = 0; m < NMIX; m++) {
            float s = 0.f;
#pragma unroll
            for (int ch = 0; ch < NJC; ch++) s += g_facc[bc][ch][m][i];
            tif[m] = s + ZITTERf * yi;
        }
        tif[NMIX] = yi;

#pragma unroll
        for (int k = 0; k < H; k++) {
            float s = b1[k];
#pragma unroll
            for (int t = 0; t < NMIX + 1; t++) s = fmaf(W1[k * (NMIX + 1) + t], tif[t], s);
            sh2[tid * H + k] = fmaxf(s, 0.f);
        }
        __syncthreads();

        if (tid < H) {
            float s = 0.f;
            for (int t = 0; t < 128; t++) s += sh2[t * H + tid];
            g_hpart[bc][tile][tid] = s;
        }
        __syncthreads();
        if (tid == 0) { __threadfence(); atomicAdd(&g_c1, 1); }
    }

    // ================= phase B: block 0 runs the MLP =================
    if (bid == 0) {
        if (tid == 0) {
            while (atomicAdd(&g_c1, 0) < FEAT2_BLOCKS) { __nanosleep(64); }
            __threadfence();
        }
        __syncthreads();

        if (tid < NB * NCH) {
            int b = tid / NCH, c = tid % NCH;
            for (int k = 0; k < H; k++) {
                float s = 0.f;
#pragma unroll
                for (int tt = 0; tt < NT2; tt++) s += g_hpart[b * NCH + c][tt][k];
                sh_h0[b][c * H + k] = s * (1.0f / ND);
            }
        }
        if (tid < NCH) {
            float l = fminf(fmaxf(likerr[tid], 0.1f), 1.0f);
            g_diag[tid] = ZITTERf + l * l;
        }
        __syncthreads();

        if (tid < NB * H) {                       // layer 2
            int b = tid / H, k = tid % H;
            float s = b2[k];
            for (int u = 0; u < NCH * H; u++) s = fmaf(W2[k * (NCH * H) + u], sh_h0[b][u], s);
            sh_a[b][k] = fmaxf(s, 0.f);
        }
        __syncthreads();
        if (tid < NB * H) {                       // layer 3
            int b = tid / H, k = tid % H;
            float s = b3[k];
            for (int u = 0; u < H; u++) s = fmaf(W3[k * H + u], sh_a[b][u], s);
            sh_b[b][k] = fmaxf(s, 0.f);
        }
        __syncthreads();
        if (tid < NB * H) {                       // layer 4
            int b = tid / H, k = tid % H;
            float s = b4[k];
            for (int u = 0; u < H; u++) s = fmaf(W4[k * H + u], sh_b[b][u], s);
            sh_a[b][k] = fmaxf(s, 0.f);
        }
        __syncthreads();
        if (tid < NB * NCH * NMIX) {              // layer 5 -> logits
            int b = tid / (NCH * NMIX), n = tid % (NCH * NMIX);
            float s = b5[n];
            for (int u = 0; u < H; u++) s = fmaf(W5[n * H + u], sh_a[b][u], s);
            sh_ll[b][n] = s;
        }
        __syncthreads();

        for (int t = tid; t < NB * NS * NCH; t += 128) {   // gumbel softmax
            int b = t / (NS * NCH);
            int rem = t % (NS * NCH);
            int s = rem / NCH, c = rem % NCH;
            float z[NMIX], mx = -1e30f;
#pragma unroll
            for (int m = 0; m < NMIX; m++) {
                float u = unif[((b * NS + s) * NCH + c) * NMIX + m];
                float g = -__logf(-__logf(u + 1e-20f));
                z[m] = (g + sh_ll[b][c * NMIX + m]) * INV_TEMP;
                mx = fmaxf(mx, z[m]);
            }
            float sum = 0.f, e[NMIX];
#pragma unroll
            for (int m = 0; m < NMIX; m++) { e[m] = __expf(z[m] - mx); sum += e[m]; }
            float inv = 1.f / sum;
#pragma unroll
            for (int m = 0; m < NMIX; m++) sh_sm[b][s][c][m] = e[m] * inv;
        }
        __syncthreads();

        if (tid < NB * NCH * NMIX) {              // mean over samples
            int b = tid / (NCH * NMIX);
            int cm = tid % (NCH * NMIX);
            int c = cm / NMIX, m = cm % NMIX;
            float s = 0.f;
#pragma unroll
            for (int ss = 0; ss < NS; ss++) s += sh_sm[b][ss][c][m];
            g_w[(b * NCH + c) * NMIX + m] = s * (1.0f / NS);
        }
        __syncthreads();
        if (tid == 0) { __threadfence(); atomicExch(&g_flag, 1); }
    }

    // ============ phase C: blocks 0..371 build table entries ============
    if (tid == 0) {
        while (atomicAdd(&g_flag, 0) == 0) { __nanosleep(64); }
        __threadfence();
    }
    __syncthreads();

    {
        int idx = bid * 128 + tid;                // 372*128 = 47616 = 24*1984
        int bc  = idx / TBLP;
        int k   = idx % TBLP;
        float d0 = (float)k * (1.0f / TSCALE);
        float d1 = (float)(k + 1) * (1.0f / TSCALE);
        float d20 = d0 * d0, d21 = d1 * d1;
        float a0 = 0.f, a1 = 0.f;
#pragma unroll
        for (int m = 0; m < NMIX; m++) {
            float iv = inv_std[m];
            float a  = -0.5f * PI2f * PI2f * iv * iv * LOG2E;
            float p  = PI2f * mu[m];
            float w  = g_w[bc * NMIX + m];
            a0 = fmaf(w, ex2f_(a * d20) * __cosf(p * d0), a0);
            a1 = fmaf(w, ex2f_(a * d21) * __cosf(p * d1), a1);
        }
        g_ftab2[bc][k] = make_float2(a0, a1);
    }
}

// ---------------------------------------------------------------------------
// Kernel 2: pure LUT output — no barriers, table ready at launch.
// block = (b, j-tile 256, i-tile 32); per element 1 LDS.64 + lerp.
// Also resets the feat sync words for the next graph replay (runs last).
// ---------------------------------------------------------------------------
__global__ void __launch_bounds__(256, 4) out_kernel(
    const float* __restrict__ xc, float* __restrict__ out)
{
    int blk = blockIdx.x;
    int tid = threadIdx.x;

    __shared__ float2 fs2[NCH * TBLP];    // 47616 B
    __shared__ float xish[IT * NCH];

    int itile = blk % (ND / IT);
    int rr_   = blk / (ND / IT);
    int jt    = rr_ % (ND / JT);
    int ob    = rr_ / (ND / JT);
    int ibase = itile * IT;
    int j     = jt * JT + tid;
    float xj0 = xc[((size_t)ob * ND + j) * NCH + 0];
    float xj1 = xc[((size_t)ob * ND + j) * NCH + 1];
    float xj2 = xc[((size_t)ob * ND + j) * NCH + 2];
    if (tid < IT * NCH)
        xish[tid] = xc[((size_t)ob * ND + ibase) * NCH + tid];

    {
        const float4* src = (const float4*)&g_ftab2[ob * NCH][0];
        float4* dst = (float4*)fs2;
        for (int q = tid; q < NCH * TBLP / 2; q += 256) dst[q] = src[q];
    }
    float dg0 = g_diag[0], dg1 = g_diag[1], dg2 = g_diag[2];
    __syncthreads();

    float* o = out + (((size_t)ob * ND + ibase) * ND + j) * NCH;

#pragma unroll 1
    for (int ii = 0; ii < IT; ii += 2) {
        int iA = ibase + ii;
        int iB = iA + 1;
        float tA0 = fminf(fabsf(xish[ii * NCH + 0] - xj0) * TSCALE, TCLAMP);
        float tA1 = fminf(fabsf(xish[ii * NCH + 1] - xj1) * TSCALE, TCLAMP);
        float tA2 = fminf(fabsf(xish[ii * NCH + 2] - xj2) * TSCALE, TCLAMP);
        float tB0 = fminf(fabsf(xish[ii * NCH + 3] - xj0) * TSCALE, TCLAMP);
        float tB1 = fminf(fabsf(xish[ii * NCH + 4] - xj1) * TSCALE, TCLAMP);
        float tB2 = fminf(fabsf(xish[ii * NCH + 5] - xj2) * TSCALE, TCLAMP);
        int kA0 = (int)tA0, kA1 = (int)tA1, kA2 = (int)tA2;
        int kB0 = (int)tB0, kB1 = (int)tB1, kB2 = (int)tB2;
        float2 pA0 = fs2[0 * TBLP + kA0];
        float2 pA1 = fs2[1 * TBLP + kA1];
        float2 pA2 = fs2[2 * TBLP + kA2];
        float2 pB0 = fs2[0 * TBLP + kB0];
        float2 pB1 = fs2[1 * TBLP + kB1];
        float2 pB2 = fs2[2 * TBLP + kB2];
        float fA0 = tA0 - (float)kA0, fA1 = tA1 - (float)kA1, fA2 = tA2 - (float)kA2;
        float fB0 = tB0 - (float)kB0, fB1 = tB1 - (float)kB1, fB2 = tB2 - (float)kB2;
        float rA0 = fmaf(fA0, pA0.y - pA0.x, pA0.x);
        float rA1 = fmaf(fA1, pA1.y - pA1.x, pA1.x);
        float rA2 = fmaf(fA2, pA2.y - pA2.x, pA2.x);
        float rB0 = fmaf(fB0, pB0.y - pB0.x, pB0.x);
        float rB1 = fmaf(fB1, pB1.y - pB1.x, pB1.x);
        float rB2 = fmaf(fB2, pB2.y - pB2.x, pB2.x);
        if (iA == j) { rA0 += dg0; rA1 += dg1; rA2 += dg2; }
        if (iB == j) { rB0 += dg0; rB1 += dg1; rB2 += dg2; }
        o[0] = rA0; o[1] = rA1; o[2] = rA2;
        o += (size_t)ND * NCH;
        o[0] = rB0; o[1] = rB1; o[2] = rB2;
        o += (size_t)ND * NCH;
    }

    // reset sync words for the next graph replay (kernel boundary publishes)
    if (blk == 0 && tid == 0) { g_c0 = 0; g_c1 = 0; g_flag = 0; }
}

extern "C" void kernel_launch(void* const* d_in, const int* in_sizes, int n_in,
                              void* d_out, int out_size)
{
    const float* xc      = (const float*)d_in[0];
    const float* yc      = (const float*)d_in[1];
    const float* mu      = (const float*)d_in[2];
    const float* inv_std = (const float*)d_in[3];
    const float* likerr  = (const float*)d_in[4];
    const float* unif    = (const float*)d_in[5];
    const float* W1 = (const float*)d_in[6];  const float* b1 = (const float*)d_in[7];
    const float* W2 = (const float*)d_in[8];  const float* b2 = (const float*)d_in[9];
    const float* W3 = (const float*)d_in[10]; const float* b3 = (const float*)d_in[11];
    const float* W4 = (const float*)d_in[12]; const float* b4 = (const float*)d_in[13];
    const float* W5 = (const float*)d_in[14]; const float* b5 = (const float*)d_in[15];

    feat_kernel<<<FEAT_BLOCKS, 128>>>(xc, yc, mu, inv_std, W1, b1, likerr, unif,
                                      W2, b2, W3, b3, W4, b4, W5, b5);
    out_kernel<<<OUT_BLOCKS, 256>>>(xc, (float*)d_out);
}

// round 12
// speedup vs baseline: 1.1257x; 1.0491x over previous
#include <cuda_runtime.h>
#include <cuda_fp16.h>
#include <math.h>

#define NB   8
#define ND   768
#define NCH  3
#define NMIX 5
#define H    10
#define NS   10
#define PI2f 6.283185307179586f
#define ZITTERf 1e-4f
#define INV_TEMP 10.0f
#define LOG2E 1.44269504088896341f

#define NJC 16              // j-chunks in feat
#define JC  48              // ND/NJC
#define ITILE 256           // i-range per feat block (2 i per thread)
#define NI_T  3             // ND/ITILE
#define FEAT_BLOCKS (NB * NCH * NI_T * NJC)   // 1152
#define NT2   6             // feat2 i-tiles of 128
#define FEAT2_BLOCKS (NB * NCH * NT2)          // 144
#define BUILD_BLOCKS 372                       // 372*128 = 47616 entries

#define JT  256             // j-tile in out kernel (== blockDim)
#define IT  32              // i-tile in out kernel (ND/IT = 24)
#define OUT_BLOCKS (NB * (ND / JT) * (ND / IT))   // 576

#define TBLP   1984         // half2 pair-entries per (b,c); 3*TBLP*4 = 23808B shared
#define TSCALE 220.0f       // entries per unit |d| (covers |d| <= 9.0)
#define TCLAMP 1982.0f

// cross-kernel scratch (__device__ globals per allocation rules)
__device__ float g_facc[NB * NCH][NJC][NMIX][ND];   // feat partials, coalesced in i
__device__ float g_hpart[NB * NCH][NT2][H];
__device__ float g_w[NB * NCH * NMIX];
__device__ float g_diag[NCH];
__device__ __align__(16) __half2 g_ftab2[NB * NCH][TBLP];
__device__ int g_c0;    // feat main-work completions (target 1152)
__device__ int g_c1;    // feat2 completions (target 144)
__device__ int g_flag;  // weights ready

__device__ __forceinline__ float ex2f_(float x) {
    float y; asm("ex2.approx.f32 %0, %1;" : "=f"(y) : "f"(x)); return y;
}

// ---------------------------------------------------------------------------
// Kernel 1: feat main (all 1152 blocks) -> tail phases on low-indexed blocks:
//   blocks 0..143  : feat2 (layer-1 + i-reduction) after all main work done
//   block  0       : MLP layers 2-5 + Gumbel weights + diag
//   blocks 0..371  : build the half2 pair-packed lookup tables (128 ent each)
// All spinner blocks (0..371) are first-wave resident (1152 <= 1184 slots at
// __launch_bounds__(128,8)) -> no deadlock. Sync words reset by out_kernel.
// ---------------------------------------------------------------------------
__global__ void __launch_bounds__(128, 8) feat_kernel(
    const float* __restrict__ xc, const float* __restrict__ yc,
    const float* __restrict__ mu, const float* __restrict__ inv_std,
    const float* __restrict__ W1, const float* __restrict__ b1,
    const float* __restrict__ likerr, const float* __restrict__ unif,
    const float* __restrict__ W2, const float* __restrict__ b2,
    const float* __restrict__ W3, const float* __restrict__ b3,
    const float* __restrict__ W4, const float* __restrict__ b4,
    const float* __restrict__ W5, const float* __restrict__ b5)
{
    int bid = blockIdx.x;
    int tid = threadIdx.x;

    __shared__ float4 jt[JC][3];                 // 2304 B (feat main)
    __shared__ float sh2[128 * H];               // 5120 B (feat2 reduction)
    __shared__ float sh_h0[NB][NCH * H];         // MLP scratch
    __shared__ float sh_a[NB][H];
    __shared__ float sh_b[NB][H];
    __shared__ float sh_ll[NB][NCH * NMIX];
    __shared__ float sh_sm[NB][NS][NCH][NMIX];

    // ================= main pairwise reduction =================
    {
        int chunk = bid % NJC;
        int r     = bid / NJC;
        int tile  = r % NI_T;
        int bc    = r / NI_T;
        int c     = bc % NCH;
        int b     = bc / NCH;

        float km2[NMIX], pm[NMIX];
#pragma unroll
        for (int m = 0; m < NMIX; m++) {
            float iv = inv_std[m];
            km2[m] = -0.5f * PI2f * PI2f * iv * iv * LOG2E;
            pm[m]  = PI2f * mu[m];
        }

        int j0 = chunk * JC;
        if (tid < JC) {
            float xv = xc[(b * ND + j0 + tid) * NCH + c];
            float yv = yc[(b * ND + j0 + tid) * NCH + c];
            float cy[NMIX], sy[NMIX];
#pragma unroll
            for (int m = 0; m < NMIX; m++) {
                float s, co;
                __sincosf(pm[m] * xv, &s, &co);
                cy[m] = co * yv;
                sy[m] = s * yv;
            }
            jt[tid][0] = make_float4(cy[0], cy[1], cy[2], cy[3]);
            jt[tid][1] = make_float4(cy[4], sy[0], sy[1], sy[2]);
            jt[tid][2] = make_float4(sy[3], sy[4], xv, 0.f);
        }

        int i0 = tile * ITILE + tid;
        int i1 = i0 + 128;
        float xi0 = xc[(b * ND + i0) * NCH + c];
        float xi1 = xc[(b * ND + i1) * NCH + c];

        float A0[NMIX], B0[NMIX], A1[NMIX], B1[NMIX];
#pragma unroll
        for (int m = 0; m < NMIX; m++) { A0[m] = B0[m] = A1[m] = B1[m] = 0.f; }
        __syncthreads();

#pragma unroll 2
        for (int j = 0; j < JC; j++) {
            float4 t0 = jt[j][0];
            float4 t1 = jt[j][1];
            float4 t2 = jt[j][2];
            float cy[NMIX] = {t0.x, t0.y, t0.z, t0.w, t1.x};
            float sy[NMIX] = {t1.y, t1.z, t1.w, t2.x, t2.y};
            float xj = t2.z;
            float d0 = xi0 - xj, d20 = d0 * d0;
            float d1 = xi1 - xj, d21 = d1 * d1;
#pragma unroll
            for (int m = 0; m < NMIX; m++) {
                float e0 = ex2f_(km2[m] * d20);
                float e1 = ex2f_(km2[m] * d21);
                A0[m] = fmaf(e0, cy[m], A0[m]);
                B0[m] = fmaf(e0, sy[m], B0[m]);
                A1[m] = fmaf(e1, cy[m], A1[m]);
                B1[m] = fmaf(e1, sy[m], B1[m]);
            }
        }

#pragma unroll
        for (int m = 0; m < NMIX; m++) {
            float s0, c0, s1, c1;
            __sincosf(pm[m] * xi0, &s0, &c0);
            __sincosf(pm[m] * xi1, &s1, &c1);
            g_facc[bc][chunk][m][i0] = fmaf(c0, A0[m], s0 * B0[m]);
            g_facc[bc][chunk][m][i1] = fmaf(c1, A1[m], s1 * B1[m]);
        }
    }
    __syncthreads();
    if (tid == 0) { __threadfence(); atomicAdd(&g_c0, 1); }

    if (bid >= BUILD_BLOCKS) return;   // high blocks exit, freeing slots

    // ================= phase A: feat2 on blocks 0..143 =================
    if (bid < FEAT2_BLOCKS) {
        if (tid == 0) {
            while (atomicAdd(&g_c0, 0) < FEAT_BLOCKS) { __nanosleep(64); }
            __threadfence();
        }
        __syncthreads();

        int tile = bid % NT2;
        int bc   = bid / NT2;
        int c    = bc % NCH;
        int b    = bc / NCH;
        int i    = tile * 128 + tid;

        float yi = yc[(b * ND + i) * NCH + c];
        float tif[NMIX + 1];
#pragma unroll
        for (int m = 0; m < NMIX; m++) {
            float s = 0.f;
#pragma unroll
            for (int ch = 0; ch < NJC; ch++) s += g_facc[bc][ch][m][i];
            tif[m] = s + ZITTERf * yi;
        }
        tif[NMIX] = yi;

#pragma unroll
        for (int k = 0; k < H; k++) {
            float s = b1[k];
#pragma unroll
            for (int t = 0; t < NMIX + 1; t++) s = fmaf(W1[k * (NMIX + 1) + t], tif[t], s);
            sh2[tid * H + k] = fmaxf(s, 0.f);
        }
        __syncthreads();

        if (tid < H) {
            float s = 0.f;
            for (int t = 0; t < 128; t++) s += sh2[t * H + tid];
            g_hpart[bc][tile][tid] = s;
        }
        __syncthreads();
        if (tid == 0) { __threadfence(); atomicAdd(&g_c1, 1); }
    }

    // ================= phase B: block 0 runs the MLP =================
    if (bid == 0) {
        if (tid == 0) {
            while (atomicAdd(&g_c1, 0) < FEAT2_BLOCKS) { __nanosleep(64); }
            __threadfence();
        }
        __syncthreads();

        if (tid < NB * NCH) {
            int b = tid / NCH, c = tid % NCH;
            for (int k = 0; k < H; k++) {
                float s = 0.f;
#pragma unroll
                for (int tt = 0; tt < NT2; tt++) s += g_hpart[b * NCH + c][tt][k];
                sh_h0[b][c * H + k] = s * (1.0f / ND);
            }
        }
        if (tid < NCH) {
            float l = fminf(fmaxf(likerr[tid], 0.1f), 1.0f);
            g_diag[tid] = ZITTERf + l * l;
        }
        __syncthreads();

        if (tid < NB * H) {                       // layer 2
            int b = tid / H, k = tid % H;
            float s = b2[k];
            for (int u = 0; u < NCH * H; u++) s = fmaf(W2[k * (NCH * H) + u], sh_h0[b][u], s);
            sh_a[b][k] = fmaxf(s, 0.f);
        }
        __syncthreads();
        if (tid < NB * H) {                       // layer 3
            int b = tid / H, k = tid % H;
            float s = b3[k];
            for (int u = 0; u < H; u++) s = fmaf(W3[k * H + u], sh_a[b][u], s);
            sh_b[b][k] = fmaxf(s, 0.f);
        }
        __syncthreads();
        if (tid < NB * H) {                       // layer 4
            int b = tid / H, k = tid % H;
            float s = b4[k];
            for (int u = 0; u < H; u++) s = fmaf(W4[k * H + u], sh_b[b][u], s);
            sh_a[b][k] = fmaxf(s, 0.f);
        }
        __syncthreads();
        if (tid < NB * NCH * NMIX) {              // layer 5 -> logits
            int b = tid / (NCH * NMIX), n = tid % (NCH * NMIX);
            float s = b5[n];
            for (int u = 0; u < H; u++) s = fmaf(W5[n * H + u], sh_a[b][u], s);
            sh_ll[b][n] = s;
        }
        __syncthreads();

        for (int t = tid; t < NB * NS * NCH; t += 128) {   // gumbel softmax
            int b = t / (NS * NCH);
            int rem = t % (NS * NCH);
            int s = rem / NCH, c = rem % NCH;
            float z[NMIX], mx = -1e30f;
#pragma unroll
            for (int m = 0; m < NMIX; m++) {
                float u = unif[((b * NS + s) * NCH + c) * NMIX + m];
                float g = -__logf(-__logf(u + 1e-20f));
                z[m] = (g + sh_ll[b][c * NMIX + m]) * INV_TEMP;
                mx = fmaxf(mx, z[m]);
            }
            float sum = 0.f, e[NMIX];
#pragma unroll
            for (int m = 0; m < NMIX; m++) { e[m] = __expf(z[m] - mx); sum += e[m]; }
            float inv = 1.f / sum;
#pragma unroll
            for (int m = 0; m < NMIX; m++) sh_sm[b][s][c][m] = e[m] * inv;
        }
        __syncthreads();

        if (tid < NB * NCH * NMIX) {              // mean over samples
            int b = tid / (NCH * NMIX);
            int cm = tid % (NCH * NMIX);
            int c = cm / NMIX, m = cm % NMIX;
            float s = 0.f;
#pragma unroll
            for (int ss = 0; ss < NS; ss++) s += sh_sm[b][ss][c][m];
            g_w[(b * NCH + c) * NMIX + m] = s * (1.0f / NS);
        }
        __syncthreads();
        if (tid == 0) { __threadfence(); atomicExch(&g_flag, 1); }
    }

    // ============ phase C: blocks 0..371 build table entries ============
    if (tid == 0) {
        while (atomicAdd(&g_flag, 0) == 0) { __nanosleep(64); }
        __threadfence();
    }
    __syncthreads();

    {
        int idx = bid * 128 + tid;                // 372*128 = 47616 = 24*1984
        int bc  = idx / TBLP;
        int k   = idx % TBLP;
        float d0 = (float)k * (1.0f / TSCALE);
        float d1 = (float)(k + 1) * (1.0f / TSCALE);
        float d20 = d0 * d0, d21 = d1 * d1;
        float a0 = 0.f, a1 = 0.f;
#pragma unroll
        for (int m = 0; m < NMIX; m++) {
            float iv = inv_std[m];
            float a  = -0.5f * PI2f * PI2f * iv * iv * LOG2E;
            float p  = PI2f * mu[m];
            float w  = g_w[bc * NMIX + m];
            a0 = fmaf(w, ex2f_(a * d20) * __cosf(p * d0), a0);
            a1 = fmaf(w, ex2f_(a * d21) * __cosf(p * d1), a1);
        }
        g_ftab2[bc][k] = __floats2half2_rn(a0, a1);
    }
}

// ---------------------------------------------------------------------------
// Kernel 2: pure LUT output — no barriers, table ready at launch.
// half2 pair-packed table: 1 LDS.32 per lookup (1 bank/lane), 23.8KB shared.
// block = (b, j-tile 256, i-tile 32). Resets feat sync words (runs last).
// ---------------------------------------------------------------------------
__global__ void __launch_bounds__(256, 6) out_kernel(
    const float* __restrict__ xc, float* __restrict__ out)
{
    int blk = blockIdx.x;
    int tid = threadIdx.x;

    __shared__ __half2 fs2[NCH * TBLP];   // 23808 B
    __shared__ float xish[IT * NCH];

    int itile = blk % (ND / IT);
    int rr_   = blk / (ND / IT);
    int jt    = rr_ % (ND / JT);
    int ob    = rr_ / (ND / JT);
    int ibase = itile * IT;
    int j     = jt * JT + tid;
    float xj0 = xc[((size_t)ob * ND + j) * NCH + 0];
    float xj1 = xc[((size_t)ob * ND + j) * NCH + 1];
    float xj2 = xc[((size_t)ob * ND + j) * NCH + 2];
    if (tid < IT * NCH)
        xish[tid] = xc[((size_t)ob * ND + ibase) * NCH + tid];

    {
        const float4* src = (const float4*)&g_ftab2[ob * NCH][0];
        float4* dst = (float4*)fs2;
        for (int q = tid; q < NCH * TBLP / 4; q += 256) dst[q] = src[q];
    }
    float dg0 = g_diag[0], dg1 = g_diag[1], dg2 = g_diag[2];
    __syncthreads();

    float* o = out + (((size_t)ob * ND + ibase) * ND + j) * NCH;

#pragma unroll 1
    for (int ii = 0; ii < IT; ii += 2) {
        int iA = ibase + ii;
        int iB = iA + 1;
        float tA0 = fminf(fabsf(xish[ii * NCH + 0] - xj0) * TSCALE, TCLAMP);
        float tA1 = fminf(fabsf(xish[ii * NCH + 1] - xj1) * TSCALE, TCLAMP);
        float tA2 = fminf(fabsf(xish[ii * NCH + 2] - xj2) * TSCALE, TCLAMP);
        float tB0 = fminf(fabsf(xish[ii * NCH + 3] - xj0) * TSCALE, TCLAMP);
        float tB1 = fminf(fabsf(xish[ii * NCH + 4] - xj1) * TSCALE, TCLAMP);
        float tB2 = fminf(fabsf(xish[ii * NCH + 5] - xj2) * TSCALE, TCLAMP);
        int kA0 = (int)tA0, kA1 = (int)tA1, kA2 = (int)tA2;
        int kB0 = (int)tB0, kB1 = (int)tB1, kB2 = (int)tB2;
        float2 pA0 = __half22float2(fs2[0 * TBLP + kA0]);
        float2 pA1 = __half22float2(fs2[1 * TBLP + kA1]);
        float2 pA2 = __half22float2(fs2[2 * TBLP + kA2]);
        float2 pB0 = __half22float2(fs2[0 * TBLP + kB0]);
        float2 pB1 = __half22float2(fs2[1 * TBLP + kB1]);
        float2 pB2 = __half22float2(fs2[2 * TBLP + kB2]);
        float fA0 = tA0 - (float)kA0, fA1 = tA1 - (float)kA1, fA2 = tA2 - (float)kA2;
        float fB0 = tB0 - (float)kB0, fB1 = tB1 - (float)kB1, fB2 = tB2 - (float)kB2;
        float rA0 = fmaf(fA0, pA0.y - pA0.x, pA0.x);
        float rA1 = fmaf(fA1, pA1.y - pA1.x, pA1.x);
        float rA2 = fmaf(fA2, pA2.y - pA2.x, pA2.x);
        float rB0 = fmaf(fB0, pB0.y - pB0.x, pB0.x);
        float rB1 = fmaf(fB1, pB1.y - pB1.x, pB1.x);
        float rB2 = fmaf(fB2, pB2.y - pB2.x, pB2.x);
        if (iA == j) { rA0 += dg0; rA1 += dg1; rA2 += dg2; }
        if (iB == j) { rB0 += dg0; rB1 += dg1; rB2 += dg2; }
        o[0] = rA0; o[1] = rA1; o[2] = rA2;
        o += (size_t)ND * NCH;
        o[0] = rB0; o[1] = rB1; o[2] = rB2;
        o += (size_t)ND * NCH;
    }

    // reset sync words for the next graph replay (kernel boundary publishes)
    if (blk == 0 && tid == 0) { g_c0 = 0; g_c1 = 0; g_flag = 0; }
}

extern "C" void kernel_launch(void* const* d_in, const int* in_sizes, int n_in,
                              void* d_out, int out_size)
{
    const float* xc      = (const float*)d_in[0];
    const float* yc      = (const float*)d_in[1];
    const float* mu      = (const float*)d_in[2];
    const float* inv_std = (const float*)d_in[3];
    const float* likerr  = (const float*)d_in[4];
    const float* unif    = (const float*)d_in[5];
    const float* W1 = (const float*)d_in[6];  const float* b1 = (const float*)d_in[7];
    const float* W2 = (const float*)d_in[8];  const float* b2 = (const float*)d_in[9];
    const float* W3 = (const float*)d_in[10]; const float* b3 = (const float*)d_in[11];
    const float* W4 = (const float*)d_in[12]; const float* b4 = (const float*)d_in[13];
    const float* W5 = (const float*)d_in[14]; const float* b5 = (const float*)d_in[15];

    feat_kernel<<<FEAT_BLOCKS, 128>>>(xc, yc, mu, inv_std, W1, b1, likerr, unif,
                                      W2, b2, W3, b3, W4, b4, W5, b5);
    out_kernel<<<OUT_BLOCKS, 256>>>(xc, (float*)d_out);
}